// round 1
// baseline (speedup 1.0000x reference)
#include <cuda_runtime.h>

// Problem constants: x is [32, 28, 28, 512] fp32; out is [32, 29, 29, 1] fp32.
// Only batch 0 of x is used. out[b,i,j] identical across b.
#define HH    28
#define WW    28
#define CC    512
#define NPOS  (HH * WW)      // 784 spatial positions
#define OD    29             // H+1 = W+1
#define OUT2D (OD * OD)      // 841
#define BATCH 32
#define NTHREADS 128

// Scratch: channel-summed squared filter, one float per (h,w).
__device__ float        g_fsq[NPOS];
__device__ unsigned int g_count = 0;

__global__ void __launch_bounds__(NTHREADS)
b_squared_kernel(const float* __restrict__ x, float* __restrict__ out) {
    const int p   = blockIdx.x;    // spatial position 0..783
    const int tid = threadIdx.x;

    // ---------------- Phase 1: fsq[p] = sum_c x[0,p,c]^2 ----------------
    // 128 threads x float4 = 512 channels, fully coalesced.
    const float4 v = reinterpret_cast<const float4*>(x + (size_t)p * CC)[tid];
    float s = v.x * v.x + v.y * v.y + v.z * v.z + v.w * v.w;

    #pragma unroll
    for (int o = 16; o > 0; o >>= 1)
        s += __shfl_xor_sync(0xffffffffu, s, o);

    __shared__ float warp_s[NTHREADS / 32];
    __shared__ bool  is_last;
    const int wid = tid >> 5, lid = tid & 31;
    if (lid == 0) warp_s[wid] = s;
    __syncthreads();

    if (tid == 0) {
        g_fsq[p] = warp_s[0] + warp_s[1] + warp_s[2] + warp_s[3];
        __threadfence();  // make g_fsq[p] globally visible before the atomic
        unsigned int old = atomicAdd(&g_count, 1u);
        is_last = (old == (unsigned int)(gridDim.x - 1));
    }
    __syncthreads();
    if (!is_last) return;

    // ---------------- Phase 2: last block does integral image + output ----------------
    __threadfence();

    __shared__ float fsq_s[NPOS];
    __shared__ float I[OD][OD + 1];   // +1 pad vs bank conflicts
    __shared__ float o2[OUT2D];

    // Pull fsq via L2 (bypass L1 in case of staleness; first touch anyway).
    for (int k = tid; k < NPOS; k += NTHREADS)
        fsq_s[k] = __ldcg(&g_fsq[k]);
    __syncthreads();

    // Zero borders, row cumsums.
    if (tid < OD) { I[tid][0] = 0.f; I[0][tid] = 0.f; }
    if (tid < HH) {
        float run = 0.f;
        #pragma unroll
        for (int c = 0; c < WW; ++c) {
            run += fsq_s[tid * WW + c];
            I[tid + 1][c + 1] = run;
        }
    }
    __syncthreads();

    // Column cumsums (one thread per column 1..28).
    if (tid < WW) {
        const int c = tid + 1;
        float run = 0.f;
        #pragma unroll
        for (int r = 1; r <= HH; ++r) {
            run += I[r][c];
            I[r][c] = run;
        }
    }
    __syncthreads();

    // Box sums: for output (i,j), window rows [r0,r1), cols [c0,c1).
    for (int k = tid; k < OUT2D; k += NTHREADS) {
        const int i = k / OD, j = k % OD;
        const int r0 = min(max(HH / 2 - i, 0), HH);          // clip(14-i, 0, 28)
        const int r1 = min(max(HH / 2 + HH - i, 0), HH);     // clip(42-i, 0, 28)
        const int c0 = min(max(WW / 2 - j, 0), WW);
        const int c1 = min(max(WW / 2 + WW - j, 0), WW);
        o2[k] = I[r1][c1] - I[r0][c1] - I[r1][c0] + I[r0][c0];
    }
    __syncthreads();

    // Broadcast to all 32 batch elements (output is contiguous [32,841]).
    const int total = BATCH * OUT2D;
    for (int k = tid; k < total; k += NTHREADS)
        out[k] = o2[k % OUT2D];

    // Reset counter for the next graph replay (all other blocks already done).
    if (tid == 0) g_count = 0;
}

extern "C" void kernel_launch(void* const* d_in, const int* in_sizes, int n_in,
                              void* d_out, int out_size) {
    const float* x  = (const float*)d_in[0];
    float* out      = (float*)d_out;
    b_squared_kernel<<<NPOS, NTHREADS>>>(x, out);
}

// round 2
// speedup vs baseline: 1.5018x; 1.5018x over previous
#include <cuda_runtime.h>

// x: [32, 28, 28, 512] fp32 (only batch 0 used); out: [32, 29, 29, 1] fp32.
#define HH    28
#define WW    28
#define CC    512
#define NPOS  (HH * WW)      // 784
#define OD    29
#define OUT2D (OD * OD)      // 841
#define BATCH 32

// Scratch: channel-summed squared filter, one float per (h,w).
__device__ float g_fsq[NPOS];

// ---------------- Kernel 1: fsq[p] = sum_c x[0,p,c]^2 ----------------
__global__ void __launch_bounds__(128)
fsq_kernel(const float* __restrict__ x) {
    const int p   = blockIdx.x;
    const int tid = threadIdx.x;

    const float4 v = reinterpret_cast<const float4*>(x + (size_t)p * CC)[tid];
    float s = v.x * v.x + v.y * v.y + v.z * v.z + v.w * v.w;

    #pragma unroll
    for (int o = 16; o > 0; o >>= 1)
        s += __shfl_xor_sync(0xffffffffu, s, o);

    __shared__ float warp_s[4];
    const int wid = tid >> 5, lid = tid & 31;
    if (lid == 0) warp_s[wid] = s;
    __syncthreads();
    if (tid == 0)
        g_fsq[p] = warp_s[0] + warp_s[1] + warp_s[2] + warp_s[3];
}

// ---------------- Kernel 2: integral image + box sums, 1 block per batch ----------------
__global__ void __launch_bounds__(256)
boxsum_kernel(float* __restrict__ out) {
    const int tid = threadIdx.x;
    const int b   = blockIdx.x;

    __shared__ float fsq_s[NPOS];
    __shared__ float I[OD][OD + 3];   // padded rows to dodge bank conflicts

    // Load fsq (784 floats; L2 hits after kernel-1). 256 threads -> 4 iters.
    #pragma unroll
    for (int k = tid; k < NPOS; k += 256)
        fsq_s[k] = g_fsq[k];

    // Zero borders.
    if (tid < OD) { I[tid][0] = 0.f; I[0][tid] = 0.f; }
    __syncthreads();

    // Row cumsums: thread r handles row r (28 threads).
    if (tid < HH) {
        float run = 0.f;
        #pragma unroll
        for (int c = 0; c < WW; ++c) {
            run += fsq_s[tid * WW + c];
            I[tid + 1][c + 1] = run;
        }
    }
    __syncthreads();

    // Column cumsums: thread c handles column c+1; running sum stays in a
    // register, the I[r][c] loads are independent and pipeline.
    if (tid < WW) {
        const int c = tid + 1;
        float run = 0.f;
        #pragma unroll
        for (int r = 1; r <= HH; ++r) {
            run += I[r][c];
            I[r][c] = run;
        }
    }
    __syncthreads();

    // Each thread computes box sums directly and stores to its batch slice.
    float* ob = out + (size_t)b * OUT2D;
    #pragma unroll
    for (int k = tid; k < OUT2D; k += 256) {
        const int i = k / OD, j = k - i * OD;
        const int r0 = min(max(HH / 2 - i, 0), HH);
        const int r1 = min(max(HH / 2 + HH - i, 0), HH);
        const int c0 = min(max(WW / 2 - j, 0), WW);
        const int c1 = min(max(WW / 2 + WW - j, 0), WW);
        ob[k] = I[r1][c1] - I[r0][c1] - I[r1][c0] + I[r0][c0];
    }
}

extern "C" void kernel_launch(void* const* d_in, const int* in_sizes, int n_in,
                              void* d_out, int out_size) {
    const float* x = (const float*)d_in[0];
    float* out     = (float*)d_out;
    fsq_kernel<<<NPOS, 128>>>(x);
    boxsum_kernel<<<BATCH, 256>>>(out);
}